// round 14
// baseline (speedup 1.0000x reference)
#include <cuda_runtime.h>
#include <cuda_fp16.h>
#include <math.h>
#include <stdint.h>

#define HIDDEN   1024
#define HEADS    16
#define HEAD_DIM 64
#define MLPH     4096
#define BB       2
#define LL       2048
#define NTOK     (BB*LL)          // 4096
#define W1N      (3*HIDDEN+MLPH)  // 7168

// ---------------- scratch (static device globals; no runtime alloc) ------------
__device__ float  g_mod[BB*3*HIDDEN];                   // shift|scale|gate
__device__ float  g_modp[16*BB*3*HIDDEN];               // split-K partials
__device__ float  g_part[(size_t)NTOK*HIDDEN];          // GEMM2 K-split partial
__device__ __half g_xmod[NTOK*HIDDEN];                  // fp16 LN output
__device__ __half g_h[(size_t)NTOK*W1N];                // fp16 qkv|mlp
__device__ __half g_qh[(size_t)BB*HEADS*LL*HEAD_DIM];   // roped q (pre-scaled)
__device__ __half g_kh[(size_t)BB*HEADS*LL*HEAD_DIM];   // roped k
__device__ __half g_y[(size_t)NTOK*2*HIDDEN];           // attn | tanh-mlp (fp16)
__device__ __half g_w1t[(size_t)W1N*HIDDEN];            // w1^T  [7168][1024]
__device__ __half g_wmlpt[(size_t)HIDDEN*MLPH];         // w_mlp^T [1024][4096]
__device__ __half g_w2t[(size_t)HIDDEN*2*HIDDEN];       // w2^T  [1024][2048]

// =================== helpers ====================================================
__device__ __forceinline__ uint32_t smem_u32(const void* p) {
    uint32_t a;
    asm("{ .reg .u64 t; cvta.to.shared.u64 t, %1; cvt.u32.u64 %0, t; }"
        : "=r"(a) : "l"(p));
    return a;
}
__device__ __forceinline__ uint32_t pack_f16(float lo, float hi) {
    uint32_t r;
    asm("cvt.rn.f16x2.f32 %0, %1, %2;" : "=r"(r) : "f"(hi), "f"(lo));
    return r;
}
__device__ __forceinline__ void mma_f16(float* c, const uint32_t* a, const uint32_t* b) {
    asm volatile(
        "mma.sync.aligned.m16n8k16.row.col.f32.f16.f16.f32 "
        "{%0,%1,%2,%3}, {%4,%5,%6,%7}, {%8,%9}, {%0,%1,%2,%3};"
        : "+f"(c[0]), "+f"(c[1]), "+f"(c[2]), "+f"(c[3])
        : "r"(a[0]), "r"(a[1]), "r"(a[2]), "r"(a[3]), "r"(b[0]), "r"(b[1]));
}
__device__ __forceinline__ void ldm_x4(uint32_t* r, uint32_t addr) {
    asm volatile("ldmatrix.sync.aligned.m8n8.x4.shared.b16 {%0,%1,%2,%3}, [%4];"
        : "=r"(r[0]), "=r"(r[1]), "=r"(r[2]), "=r"(r[3]) : "r"(addr));
}
__device__ __forceinline__ void ldm_x4_t(uint32_t* r, uint32_t addr) {
    asm volatile("ldmatrix.sync.aligned.m8n8.x4.trans.shared.b16 {%0,%1,%2,%3}, [%4];"
        : "=r"(r[0]), "=r"(r[1]), "=r"(r[2]), "=r"(r[3]) : "r"(addr));
}
__device__ __forceinline__ void cp16(uint32_t dst, const void* src) {
    asm volatile("cp.async.cg.shared.global [%0], [%1], 16;" :: "r"(dst), "l"(src));
}
__device__ __forceinline__ void cp_commit() {
    asm volatile("cp.async.commit_group;" ::: "memory");
}
template<int N>
__device__ __forceinline__ void cp_wait() {
    asm volatile("cp.async.wait_group %0;" :: "n"(N) : "memory");
}

// =================== transpose + convert: f32[K][N] -> f16[N][K] ================
__global__ void __launch_bounds__(256) transpose_h(
        const float* __restrict__ in, __half* __restrict__ out, int K, int N) {
    __shared__ float tile[32][33];
    const int n0 = blockIdx.x << 5, k0 = blockIdx.y << 5;
    const int tx = threadIdx.x, ty = threadIdx.y;
    #pragma unroll
    for (int i = 0; i < 4; i++)
        tile[ty + (i << 3)][tx] = in[(size_t)(k0 + ty + (i << 3)) * N + n0 + tx];
    __syncthreads();
    #pragma unroll
    for (int i = 0; i < 4; i++)
        out[(size_t)(n0 + ty + (i << 3)) * K + k0 + tx] =
            __float2half(tile[tx][ty + (i << 3)]);
}

// =================== fp16 GEMM: cp.async 4-stage, ldmatrix, mma m16n8k16 =======
// MODE 0: +bias->half   1: tanh(+bias)->half   2: x+gate*(acc+bias)->f32
// MODE 3: raw f32 partial   4: x+gate*(acc+part+bias)->f32
static constexpr int PA = 40;                  // halves pitch (80 B)
static constexpr int TILE_B = 128 * PA * 2;    // 10240 B
static constexpr int STAGE_B = 2 * TILE_B;     // 20480 B
static constexpr uint32_t GEMM_SMEM = 4 * STAGE_B;   // 81920 B

__device__ __forceinline__ void gemm_issue(
        const __half* __restrict__ A, int lda,
        const __half* __restrict__ Bt, int ldb,
        int bm, int bn, int kt, int slot, uint32_t sbase, int tid) {
    const uint32_t dA = sbase + slot * STAGE_B;
    const __half* Ag = A + (size_t)bm * lda + (kt << 5);
    #pragma unroll
    for (int i = 0; i < 2; i++) {
        int idx = (i << 8) + tid;
        int r = idx >> 2, q = idx & 3;
        cp16(dA + r * 80 + (q << 4), Ag + (size_t)r * lda + (q << 3));
    }
    const uint32_t dB = dA + TILE_B;
    const __half* Bg = Bt + (size_t)bn * ldb + (kt << 5);
    #pragma unroll
    for (int i = 0; i < 2; i++) {
        int idx = (i << 8) + tid;
        int r = idx >> 2, q = idx & 3;
        cp16(dB + r * 80 + (q << 4), Bg + (size_t)r * ldb + (q << 3));
    }
    cp_commit();
}

template<int MODE>
__global__ void __launch_bounds__(256, 2) mma_gemm(
        const __half* __restrict__ A, int lda,
        const __half* __restrict__ Bt, int ldb,
        void* __restrict__ Cv, int ldc, int K,
        const float* __restrict__ bias,
        const float* __restrict__ xres,
        const float* __restrict__ mod,
        const float* __restrict__ part) {
    extern __shared__ char smc[];
    const uint32_t sbase = smem_u32(smc);

    const int tid  = threadIdx.x;
    const int warp = tid >> 5;
    const int lane = tid & 31;
    const int g = lane >> 2, t = lane & 3;
    const int wm = (warp >> 2) * 64;
    const int wn = (warp & 3) * 32;
    const int bm = blockIdx.y << 7;
    const int bn = blockIdx.x << 7;

    const int rA = (lane & 7) + ((lane >> 3) & 1) * 8;
    const int cA = (lane >> 4) * 8;
    const int rB = (lane & 7) + (lane >> 4) * 8;
    const int cB = ((lane >> 3) & 1) * 8;
    const uint32_t aoff = ((wm + rA) * PA + cA) * 2;
    const uint32_t boff = ((wn + rB) * PA + cB) * 2;

    float acc[4][4][4];
    #pragma unroll
    for (int i = 0; i < 4; i++)
        #pragma unroll
        for (int j = 0; j < 4; j++)
            #pragma unroll
            for (int e = 0; e < 4; e++) acc[i][j][e] = 0.0f;

    const int NT = K >> 5;
    gemm_issue(A, lda, Bt, ldb, bm, bn, 0, 0, sbase, tid);
    gemm_issue(A, lda, Bt, ldb, bm, bn, 1, 1, sbase, tid);
    gemm_issue(A, lda, Bt, ldb, bm, bn, 2, 2, sbase, tid);

    for (int kt = 0; kt < NT; kt++) {
        if (kt + 2 < NT)      cp_wait<2>();
        else if (kt + 1 < NT) cp_wait<1>();
        else                  cp_wait<0>();
        __syncthreads();
        if (kt + 3 < NT)
            gemm_issue(A, lda, Bt, ldb, bm, bn, kt + 3, (kt + 3) & 3, sbase, tid);

        const uint32_t sA_b = sbase + (kt & 3) * STAGE_B;
        const uint32_t sB_b = sA_b + TILE_B;
        #pragma unroll
        for (int kk = 0; kk < 2; kk++) {
            uint32_t af[4][4], bf[4][2];
            #pragma unroll
            for (int mt = 0; mt < 4; mt++)
                ldm_x4(af[mt], sA_b + aoff + ((mt * 16 * PA + kk * 16) << 1));
            #pragma unroll
            for (int ntp = 0; ntp < 2; ntp++) {
                uint32_t tmp[4];
                ldm_x4(tmp, sB_b + boff + ((ntp * 16 * PA + kk * 16) << 1));
                bf[2*ntp][0]   = tmp[0]; bf[2*ntp][1]   = tmp[1];
                bf[2*ntp+1][0] = tmp[2]; bf[2*ntp+1][1] = tmp[3];
            }
            #pragma unroll
            for (int mt = 0; mt < 4; mt++)
                #pragma unroll
                for (int nt = 0; nt < 4; nt++)
                    mma_f16(acc[mt][nt], af[mt], bf[nt]);
        }
    }

    // ---- epilogue ----
    #pragma unroll
    for (int nt = 0; nt < 4; nt++) {
        const int col = bn + wn + (nt << 3) + (t << 1);
        float2 bi = make_float2(0.f, 0.f);
        if (MODE != 3) bi = *(const float2*)(bias + col);
        #pragma unroll
        for (int mt = 0; mt < 4; mt++) {
            const int r0 = bm + wm + (mt << 4) + g;
            float2 v0, v1;
            v0.x = acc[mt][nt][0] + bi.x;  v0.y = acc[mt][nt][1] + bi.y;
            v1.x = acc[mt][nt][2] + bi.x;  v1.y = acc[mt][nt][3] + bi.y;
            if (MODE == 1) {
                v0.x = tanhf(v0.x); v0.y = tanhf(v0.y);
                v1.x = tanhf(v1.x); v1.y = tanhf(v1.y);
            }
            if (MODE == 3) {
                float* C = (float*)Cv;
                *(float2*)(C + (size_t)r0 * ldc + col)       = v0;
                *(float2*)(C + (size_t)(r0 + 8) * ldc + col) = v1;
            } else if (MODE == 2 || MODE == 4) {
                float* C = (float*)Cv;
                const int b0 = r0 >> 11;
                const float2 g2 = *(const float2*)(mod + b0*3*HIDDEN + 2*HIDDEN + col);
                const float2 x0 = *(const float2*)(xres + (size_t)r0*HIDDEN + col);
                const float2 x1 = *(const float2*)(xres + (size_t)(r0+8)*HIDDEN + col);
                if (MODE == 4) {
                    const float2 p0 = *(const float2*)(part + (size_t)r0*HIDDEN + col);
                    const float2 p1 = *(const float2*)(part + (size_t)(r0+8)*HIDDEN + col);
                    v0.x += p0.x; v0.y += p0.y; v1.x += p1.x; v1.y += p1.y;
                }
                v0.x = fmaf(g2.x, v0.x, x0.x); v0.y = fmaf(g2.y, v0.y, x0.y);
                v1.x = fmaf(g2.x, v1.x, x1.x); v1.y = fmaf(g2.y, v1.y, x1.y);
                *(float2*)(C + (size_t)r0 * ldc + col)       = v0;
                *(float2*)(C + (size_t)(r0 + 8) * ldc + col) = v1;
            } else {
                __half* C = (__half*)Cv;
                *(uint32_t*)(C + (size_t)r0 * ldc + col)       = pack_f16(v0.x, v0.y);
                *(uint32_t*)(C + (size_t)(r0 + 8) * ldc + col) = pack_f16(v1.x, v1.y);
            }
        }
    }
}

// =================== fp16 flash attention (3-slot KV ring) =====================
static constexpr int PQ = 72;                        // halves pitch (144 B)
static constexpr int Q_BYTES  = 128 * PQ * 2;        // 18432
static constexpr int KV_SLOT  = 64 * PQ * 2;         // 9216
static constexpr uint32_t ATTN_SMEM = Q_BYTES + 6 * KV_SLOT;  // 73728

__device__ __forceinline__ void attn_issue_kv(
        const __half* __restrict__ kh, const __half* __restrict__ vg,
        int kt, int slot, uint32_t sbase, int tid) {
    #pragma unroll
    for (int i = 0; i < 2; i++) {
        const int idx = (i << 8) + tid;
        const int r = idx >> 3, q = idx & 7;
        const int row = (kt << 6) + r;
        const uint32_t dK = sbase + Q_BYTES + slot * KV_SLOT + r * 144 + (q << 4);
        cp16(dK,                kh + (size_t)row * 64  + (q << 3));
        cp16(dK + 3 * KV_SLOT,  vg + (size_t)row * W1N + (q << 3));
    }
    cp_commit();
}

__global__ void __launch_bounds__(256, 2) attn_tc(
        const __half* __restrict__ qh, const __half* __restrict__ kh,
        const __half* __restrict__ h, __half* __restrict__ y) {
    extern __shared__ char smc[];
    __half* const smh = (__half*)smc;
    const uint32_t sbase = smem_u32(smc);

    const int tid  = threadIdx.x;
    const int warp = tid >> 5;
    const int lane = tid & 31;
    const int g = lane >> 2, t = lane & 3;
    const int bh = blockIdx.y;
    const int b = bh >> 4, hd = bh & 15;
    const int q0 = blockIdx.x << 7;

    const __half* qb = qh + (size_t)bh * LL * HEAD_DIM;
    const __half* kb = kh + (size_t)bh * LL * HEAD_DIM;
    const __half* vg = h + (size_t)b * LL * W1N + 2 * HIDDEN + hd * HEAD_DIM;

    const int rK = (lane & 7) + (lane >> 4) * 8;
    const int cK = ((lane >> 3) & 1) * 8;
    const int rV = (lane & 7) + ((lane >> 3) & 1) * 8;
    const int cV = (lane >> 4) * 8;
    const uint32_t koff = (rK * PQ + cK) * 2;
    const uint32_t voff = (rV * PQ + cV) * 2;

    #pragma unroll
    for (int i = 0; i < 4; i++) {
        int idx = (i << 8) + tid;
        int r = idx >> 3, q = idx & 7;
        *(uint4*)(smh + r * PQ + (q << 3)) =
            *(const uint4*)(qb + (size_t)(q0 + r) * 64 + (q << 3));
    }
    __syncthreads();
    uint32_t qa[4][4];
    {
        const uint32_t qoff = (((warp << 4) + rV) * PQ + cV) * 2;
        #pragma unroll
        for (int kk = 0; kk < 4; kk++)
            ldm_x4(qa[kk], sbase + qoff + ((kk * 16) << 1));
    }
    __syncthreads();

    float o[8][4];
    #pragma unroll
    for (int dn = 0; dn < 8; dn++)
        #pragma unroll
        for (int e = 0; e < 4; e++) o[dn][e] = 0.0f;
    float m0 = -1e30f, m1 = -1e30f, l0 = 0.0f, l1 = 0.0f;

    attn_issue_kv(kb, vg, 0, 0, sbase, tid);
    attn_issue_kv(kb, vg, 1, 1, sbase, tid);

    const int NT = LL / 64;
    int cur = 0, nxt = 2;
    for (int kt = 0; kt < NT; kt++) {
        if (kt + 1 < NT) cp_wait<1>(); else cp_wait<0>();
        __syncthreads();
        if (kt + 2 < NT)
            attn_issue_kv(kb, vg, kt + 2, nxt, sbase, tid);

        const uint32_t sK_b = sbase + Q_BYTES + cur * KV_SLOT;
        const uint32_t sV_b = sK_b + 3 * KV_SLOT;
        cur = (cur + 1 == 3) ? 0 : cur + 1;
        nxt = (nxt + 1 == 3) ? 0 : nxt + 1;

        float s[8][4];
        #pragma unroll
        for (int nt = 0; nt < 8; nt++)
            #pragma unroll
            for (int e = 0; e < 4; e++) s[nt][e] = 0.0f;
        #pragma unroll
        for (int kk = 0; kk < 4; kk++) {
            uint32_t kf[8][2];
            #pragma unroll
            for (int ntp = 0; ntp < 4; ntp++) {
                uint32_t tmp[4];
                ldm_x4(tmp, sK_b + koff + ((ntp * 16 * PQ + kk * 16) << 1));
                kf[2*ntp][0]   = tmp[0]; kf[2*ntp][1]   = tmp[1];
                kf[2*ntp+1][0] = tmp[2]; kf[2*ntp+1][1] = tmp[3];
            }
            #pragma unroll
            for (int nt = 0; nt < 8; nt++)
                mma_f16(s[nt], qa[kk], kf[nt]);
        }

        float mx0 = -1e30f, mx1 = -1e30f;
        #pragma unroll
        for (int nt = 0; nt < 8; nt++) {
            mx0 = fmaxf(mx0, fmaxf(s[nt][0], s[nt][1]));
            mx1 = fmaxf(mx1, fmaxf(s[nt][2], s[nt][3]));
        }
        mx0 = fmaxf(mx0, __shfl_xor_sync(0xffffffffu, mx0, 1));
        mx0 = fmaxf(mx0, __shfl_xor_sync(0xffffffffu, mx0, 2));
        mx1 = fmaxf(mx1, __shfl_xor_sync(0xffffffffu, mx1, 1));
        mx1 = fmaxf(mx1, __shfl_xor_sync(0xffffffffu, mx1, 2));
        const float M0 = fmaxf(m0, mx0), M1 = fmaxf(m1, mx1);
        const float f0 = __expf(m0 - M0), f1 = __expf(m1 - M1);
        m0 = M0; m1 = M1;

        float sum0 = 0.0f, sum1 = 0.0f;
        #pragma unroll
        for (int nt = 0; nt < 8; nt++) {
            s[nt][0] = __expf(s[nt][0] - M0);
            s[nt][1] = __expf(s[nt][1] - M0);
            s[nt][2] = __expf(s[nt][2] - M1);
            s[nt][3] = __expf(s[nt][3] - M1);
            sum0 += s[nt][0] + s[nt][1];
            sum1 += s[nt][2] + s[nt][3];
        }
        sum0 += __shfl_xor_sync(0xffffffffu, sum0, 1);
        sum0 += __shfl_xor_sync(0xffffffffu, sum0, 2);
        sum1 += __shfl_xor_sync(0xffffffffu, sum1, 1);
        sum1 += __shfl_xor_sync(0xffffffffu, sum1, 2);
        l0 = l0 * f0 + sum0;
        l1 = l1 * f1 + sum1;

        #pragma unroll
        for (int dn = 0; dn < 8; dn++) {
            o[dn][0] *= f0; o[dn][1] *= f0;
            o[dn][2] *= f1; o[dn][3] *= f1;
        }

        uint32_t pa[4][4];
        #pragma unroll
        for (int kc = 0; kc < 4; kc++) {
            pa[kc][0] = pack_f16(s[2*kc][0],   s[2*kc][1]);
            pa[kc][1] = pack_f16(s[2*kc][2],   s[2*kc][3]);
            pa[kc][2] = pack_f16(s[2*kc+1][0], s[2*kc+1][1]);
            pa[kc][3] = pack_f16(s[2*kc+1][2], s[2*kc+1][3]);
        }

        #pragma unroll
        for (int kc = 0; kc < 4; kc++) {
            #pragma unroll
            for (int dnp = 0; dnp < 4; dnp++) {
                uint32_t tmp[4];
                ldm_x4_t(tmp, sV_b + voff + ((kc * 16 * PQ + dnp * 16) << 1));
                mma_f16(o[2*dnp],   pa[kc], tmp);
                mma_f16(o[2*dnp+1], pa[kc], tmp + 2);
            }
        }
    }

    const float il0 = 1.0f / l0, il1 = 1.0f / l1;
    const int row0 = b * LL + q0 + (warp << 4) + g;
    __half* yp0 = y + (size_t)row0 * (2*HIDDEN) + hd * HEAD_DIM + (t << 1);
    __half* yp1 = yp0 + (size_t)8 * (2*HIDDEN);
    #pragma unroll
    for (int dn = 0; dn < 8; dn++) {
        *(uint32_t*)(yp0 + (dn << 3)) = pack_f16(o[dn][0] * il0, o[dn][1] * il0);
        *(uint32_t*)(yp1 + (dn << 3)) = pack_f16(o[dn][2] * il1, o[dn][3] * il1);
    }
}

// ---------------- mod GEMV: split-K(16) partial + reduce ------------------------
__global__ void __launch_bounds__(256) mod_partial(
        const float* __restrict__ vec, const float* __restrict__ w_mod,
        float* __restrict__ modp) {
    __shared__ float sv[64];
    const int b = blockIdx.z, ks = blockIdx.y;
    const int n = blockIdx.x * 256 + threadIdx.x;
    if (threadIdx.x < 64) {
        float v = vec[b * HIDDEN + ks * 64 + threadIdx.x];
        sv[threadIdx.x] = v / (1.0f + expf(-v));
    }
    __syncthreads();
    float acc = 0.0f;
    const float* W = w_mod + (size_t)(ks * 64) * (3 * HIDDEN) + n;
    #pragma unroll 8
    for (int k = 0; k < 64; k++)
        acc = fmaf(sv[k], W[(size_t)k * (3 * HIDDEN)], acc);
    modp[((ks * BB) + b) * (3 * HIDDEN) + n] = acc;
}

__global__ void __launch_bounds__(256) mod_reduce(
        const float* __restrict__ modp, const float* __restrict__ b_mod,
        float* __restrict__ mod) {
    const int idx = blockIdx.x * 256 + threadIdx.x;
    const int b = idx / (3 * HIDDEN), n = idx % (3 * HIDDEN);
    float s = b_mod[n];
    #pragma unroll
    for (int ks = 0; ks < 16; ks++)
        s += modp[((ks * BB) + b) * (3 * HIDDEN) + n];
    mod[idx] = s;
}

// ---------------- kernel 2: layernorm + modulate -> fp16 ------------------------
__global__ void __launch_bounds__(256) ln_mod_kernel(const float* __restrict__ x,
                                                     const float* __restrict__ mod,
                                                     __half* __restrict__ xmod) {
    __shared__ float sbuf[8];
    __shared__ float s_mean, s_rstd;
    int token = blockIdx.x;
    int b = token >> 11;
    int tid = threadIdx.x;
    const float4 xv = ((const float4*)(x + (size_t)token*HIDDEN))[tid];

    float s = xv.x + xv.y + xv.z + xv.w;
    #pragma unroll
    for (int o = 16; o > 0; o >>= 1) s += __shfl_xor_sync(0xffffffffu, s, o);
    if ((tid & 31) == 0) sbuf[tid >> 5] = s;
    __syncthreads();
    if (tid == 0) {
        float tq = 0;
        #pragma unroll
        for (int i = 0; i < 8; i++) tq += sbuf[i];
        s_mean = tq * (1.0f / HIDDEN);
    }
    __syncthreads();
    float m = s_mean;
    float dx = xv.x - m, dy = xv.y - m, dz = xv.z - m, dw = xv.w - m;
    float ss = dx*dx + dy*dy + dz*dz + dw*dw;
    #pragma unroll
    for (int o = 16; o > 0; o >>= 1) ss += __shfl_xor_sync(0xffffffffu, ss, o);
    __syncthreads();
    if ((tid & 31) == 0) sbuf[tid >> 5] = ss;
    __syncthreads();
    if (tid == 0) {
        float tq = 0;
        #pragma unroll
        for (int i = 0; i < 8; i++) tq += sbuf[i];
        s_rstd = rsqrtf(tq * (1.0f / HIDDEN) + 1e-6f);
    }
    __syncthreads();
    float r = s_rstd;
    int c = tid * 4;
    const float4 sh = *(const float4*)(mod + b*3*HIDDEN + c);
    const float4 sc = *(const float4*)(mod + b*3*HIDDEN + HIDDEN + c);
    float o0 = fmaf(1.0f + sc.x, dx*r, sh.x);
    float o1 = fmaf(1.0f + sc.y, dy*r, sh.y);
    float o2 = fmaf(1.0f + sc.z, dz*r, sh.z);
    float o3 = fmaf(1.0f + sc.w, dw*r, sh.w);
    uint32_t* dst = (uint32_t*)(xmod + (size_t)token*HIDDEN + c);
    dst[0] = pack_f16(o0, o1);
    dst[1] = pack_f16(o2, o3);
}

// ---------------- kernel 4: RMSNorm + RoPE, fp16 h -> per-head q/k ---------------
__global__ void __launch_bounds__(512) qk_norm_rope_kernel(
        const __half* __restrict__ h,
        const float* __restrict__ pe,
        const float* __restrict__ q_scale,
        const float* __restrict__ k_scale,
        __half* __restrict__ qh, __half* __restrict__ kh) {
    int token = blockIdx.x;
    int l = token & (LL - 1);
    int b = token >> 11;
    int head = threadIdx.x >> 5;
    int lane = threadIdx.x & 31;

    const __half* hq = h + (size_t)token*W1N + head*HEAD_DIM;
    const size_t oidx = ((size_t)(b*HEADS + head)*LL + l)*HEAD_DIM + lane*2;

    const float4 p = *(const float4*)(pe + (size_t)l*128 + lane*4);
    float sx = q_scale[lane*2], sy = q_scale[lane*2+1];
    float kx = k_scale[lane*2], ky = k_scale[lane*2+1];

    {
        float2 q2 = __half22float2(*(const __half2*)(hq + lane*2));
        float ss = q2.x*q2.x + q2.y*q2.y;
        #pragma unroll
        for (int o = 16; o > 0; o >>= 1) ss += __shfl_xor_sync(0xffffffffu, ss, o);
        float rr = rsqrtf(ss * (1.0f/HEAD_DIM) + 1e-6f);
        float t0 = q2.x * rr * sx, t1 = q2.y * rr * sy;
        *(uint32_t*)(qh + oidx) =
            pack_f16(0.125f*(p.x*t0 + p.y*t1), 0.125f*(p.z*t0 + p.w*t1));
    }
    {
        float2 k2 = __half22float2(*(const __half2*)(hq + HIDDEN + lane*2));
        float ss = k2.x*k2.x + k2.y*k2.y;
        #pragma unroll
        for (int o = 16; o > 0; o >>= 1) ss += __shfl_xor_sync(0xffffffffu, ss, o);
        float rr = rsqrtf(ss * (1.0f/HEAD_DIM) + 1e-6f);
        float t0 = k2.x * rr * kx, t1 = k2.y * rr * ky;
        *(uint32_t*)(kh + oidx) = pack_f16(p.x*t0 + p.y*t1, p.z*t0 + p.w*t1);
    }
}

// ---------------- launch --------------------------------------------------------
extern "C" void kernel_launch(void* const* d_in, const int* in_sizes, int n_in,
                              void* d_out, int out_size) {
    const float* x       = (const float*)d_in[0];
    const float* vec     = (const float*)d_in[1];
    const float* pe      = (const float*)d_in[2];
    const float* w_mod   = (const float*)d_in[3];
    const float* b_mod   = (const float*)d_in[4];
    const float* w1      = (const float*)d_in[5];
    const float* b1      = (const float*)d_in[6];
    const float* w_mlp   = (const float*)d_in[7];
    const float* b_mlp   = (const float*)d_in[8];
    const float* w2      = (const float*)d_in[9];
    const float* b2      = (const float*)d_in[10];
    const float* q_scale = (const float*)d_in[11];
    const float* k_scale = (const float*)d_in[12];
    float* out = (float*)d_out;

    float *mod, *modp, *part;
    __half *xmod, *h, *qh, *kh, *y, *w1t, *wmlpt, *w2t;
    cudaGetSymbolAddress((void**)&mod,   g_mod);
    cudaGetSymbolAddress((void**)&modp,  g_modp);
    cudaGetSymbolAddress((void**)&part,  g_part);
    cudaGetSymbolAddress((void**)&xmod,  g_xmod);
    cudaGetSymbolAddress((void**)&h,     g_h);
    cudaGetSymbolAddress((void**)&qh,    g_qh);
    cudaGetSymbolAddress((void**)&kh,    g_kh);
    cudaGetSymbolAddress((void**)&y,     g_y);
    cudaGetSymbolAddress((void**)&w1t,   g_w1t);
    cudaGetSymbolAddress((void**)&wmlpt, g_wmlpt);
    cudaGetSymbolAddress((void**)&w2t,   g_w2t);

    static cudaStream_t s1 = nullptr;
    static cudaEvent_t evF = nullptr, evW1 = nullptr, evH = nullptr, evSIDE = nullptr;
    if (!s1) {
        cudaStreamCreateWithFlags(&s1, cudaStreamNonBlocking);
        cudaEventCreateWithFlags(&evF,    cudaEventDisableTiming);
        cudaEventCreateWithFlags(&evW1,   cudaEventDisableTiming);
        cudaEventCreateWithFlags(&evH,    cudaEventDisableTiming);
        cudaEventCreateWithFlags(&evSIDE, cudaEventDisableTiming);
        cudaFuncSetAttribute(mma_gemm<0>, cudaFuncAttributeMaxDynamicSharedMemorySize, GEMM_SMEM);
        cudaFuncSetAttribute(mma_gemm<1>, cudaFuncAttributeMaxDynamicSharedMemorySize, GEMM_SMEM);
        cudaFuncSetAttribute(mma_gemm<3>, cudaFuncAttributeMaxDynamicSharedMemorySize, GEMM_SMEM);
        cudaFuncSetAttribute(mma_gemm<4>, cudaFuncAttributeMaxDynamicSharedMemorySize, GEMM_SMEM);
        cudaFuncSetAttribute(attn_tc,     cudaFuncAttributeMaxDynamicSharedMemorySize, ATTN_SMEM);
    }

    // fork side stream from main (legacy) stream
    cudaEventRecord(evF, 0);
    cudaStreamWaitEvent(s1, evF, 0);

    // side: weight transposes (w1t first; it gates GEMM0)
    transpose_h<<<dim3(W1N/32, HIDDEN/32), dim3(32,8), 0, s1>>>(w1, w1t, HIDDEN, W1N);
    cudaEventRecord(evW1, s1);
    transpose_h<<<dim3(HIDDEN/32, MLPH/32),     dim3(32,8), 0, s1>>>(w_mlp, wmlpt, MLPH,     HIDDEN);
    transpose_h<<<dim3(HIDDEN/32, 2*HIDDEN/32), dim3(32,8), 0, s1>>>(w2,    w2t,   2*HIDDEN, HIDDEN);

    // main: modulation + layernorm (concurrent with transposes)
    mod_partial<<<dim3(3*HIDDEN/256, 16, BB), 256>>>(vec, w_mod, modp);
    mod_reduce<<<BB*3*HIDDEN/256, 256>>>(modp, b_mod, mod);
    ln_mod_kernel<<<NTOK, 256>>>(x, mod, xmod);

    // main: GEMM0 (full, as in R11)
    cudaStreamWaitEvent(0, evW1, 0);
    mma_gemm<0><<<dim3(W1N/128, NTOK/128), 256, GEMM_SMEM>>>(
        xmod, HIDDEN, w1t, HIDDEN, h, W1N, HIDDEN, b1, nullptr, nullptr, nullptr);
    cudaEventRecord(evH, 0);

    // side: MLP GEMM then GEMM2b (K-split partial, fills attn idle window)
    cudaStreamWaitEvent(s1, evH, 0);
    mma_gemm<1><<<dim3(HIDDEN/128, NTOK/128), 256, GEMM_SMEM, s1>>>(
        h + 3*HIDDEN, W1N, wmlpt, MLPH, y + HIDDEN, 2*HIDDEN,
        MLPH, b_mlp, nullptr, nullptr, nullptr);
    mma_gemm<3><<<dim3(HIDDEN/128, NTOK/128), 256, GEMM_SMEM, s1>>>(
        y + HIDDEN, 2*HIDDEN, w2t + HIDDEN, 2*HIDDEN, part, HIDDEN,
        HIDDEN, nullptr, nullptr, nullptr, nullptr);
    cudaEventRecord(evSIDE, s1);

    // main: rope + attention (V read directly from h inside attn)
    qk_norm_rope_kernel<<<NTOK, 512>>>(h, pe, q_scale, k_scale, qh, kh);
    attn_tc<<<dim3(LL/128, BB*HEADS), 256, ATTN_SMEM>>>(qh, kh, h, y);

    // join: GEMM2a over attn half (K=1024) + partial + fused epilogue
    cudaStreamWaitEvent(0, evSIDE, 0);
    mma_gemm<4><<<dim3(HIDDEN/128, NTOK/128), 256, GEMM_SMEM>>>(
        y, 2*HIDDEN, w2t, 2*HIDDEN, out, HIDDEN,
        HIDDEN, b2, x, mod, part);
}

// round 15
// speedup vs baseline: 1.0156x; 1.0156x over previous
#include <cuda_runtime.h>
#include <cuda_fp16.h>
#include <math.h>
#include <stdint.h>

#define HIDDEN   1024
#define HEADS    16
#define HEAD_DIM 64
#define MLPH     4096
#define BB       2
#define LL       2048
#define NTOK     (BB*LL)          // 4096
#define W1N      (3*HIDDEN+MLPH)  // 7168

// ---------------- scratch (static device globals; no runtime alloc) ------------
__device__ float  g_mod[BB*3*HIDDEN];                   // shift|scale|gate
__device__ float  g_modp[16*BB*3*HIDDEN];               // split-K partials
__device__ __half g_xmod[NTOK*HIDDEN];                  // fp16 LN output
__device__ __half g_h[(size_t)NTOK*W1N];                // fp16 qkv|mlp
__device__ __half g_qh[(size_t)BB*HEADS*LL*HEAD_DIM];   // roped q (pre-scaled)
__device__ __half g_kh[(size_t)BB*HEADS*LL*HEAD_DIM];   // roped k
__device__ __half g_y[(size_t)NTOK*2*HIDDEN];           // attn | tanh-mlp (fp16)
__device__ __half g_w1t[(size_t)W1N*HIDDEN];            // w1^T  [7168][1024]
__device__ __half g_wmlpt[(size_t)HIDDEN*MLPH];         // w_mlp^T [1024][4096]
__device__ __half g_w2t[(size_t)HIDDEN*2*HIDDEN];       // w2^T  [1024][2048]

// =================== helpers ====================================================
__device__ __forceinline__ uint32_t smem_u32(const void* p) {
    uint32_t a;
    asm("{ .reg .u64 t; cvta.to.shared.u64 t, %1; cvt.u32.u64 %0, t; }"
        : "=r"(a) : "l"(p));
    return a;
}
__device__ __forceinline__ uint32_t pack_f16(float lo, float hi) {
    uint32_t r;
    asm("cvt.rn.f16x2.f32 %0, %1, %2;" : "=r"(r) : "f"(hi), "f"(lo));
    return r;
}
__device__ __forceinline__ void mma_f16(float* c, const uint32_t* a, const uint32_t* b) {
    asm volatile(
        "mma.sync.aligned.m16n8k16.row.col.f32.f16.f16.f32 "
        "{%0,%1,%2,%3}, {%4,%5,%6,%7}, {%8,%9}, {%0,%1,%2,%3};"
        : "+f"(c[0]), "+f"(c[1]), "+f"(c[2]), "+f"(c[3])
        : "r"(a[0]), "r"(a[1]), "r"(a[2]), "r"(a[3]), "r"(b[0]), "r"(b[1]));
}
__device__ __forceinline__ void ldm_x4(uint32_t* r, uint32_t addr) {
    asm volatile("ldmatrix.sync.aligned.m8n8.x4.shared.b16 {%0,%1,%2,%3}, [%4];"
        : "=r"(r[0]), "=r"(r[1]), "=r"(r[2]), "=r"(r[3]) : "r"(addr));
}
__device__ __forceinline__ void ldm_x4_t(uint32_t* r, uint32_t addr) {
    asm volatile("ldmatrix.sync.aligned.m8n8.x4.trans.shared.b16 {%0,%1,%2,%3}, [%4];"
        : "=r"(r[0]), "=r"(r[1]), "=r"(r[2]), "=r"(r[3]) : "r"(addr));
}
__device__ __forceinline__ void cp16(uint32_t dst, const void* src) {
    asm volatile("cp.async.cg.shared.global [%0], [%1], 16;" :: "r"(dst), "l"(src));
}
__device__ __forceinline__ void cp_commit() {
    asm volatile("cp.async.commit_group;" ::: "memory");
}
template<int N>
__device__ __forceinline__ void cp_wait() {
    asm volatile("cp.async.wait_group %0;" :: "n"(N) : "memory");
}

// =================== transpose + convert: f32[K][N] -> f16[N][K] ================
// 64(k) x 32(n) tiles; fp16x2-packed 4B stores, fully coalesced both sides.
__global__ void __launch_bounds__(256) transpose_h(
        const float* __restrict__ in, __half* __restrict__ out, int K, int N) {
    __shared__ float tile[32][65];            // [n][k], pitch 65 (write conflict-free)
    const int n0 = blockIdx.x << 5, k0 = blockIdx.y << 6;
    const int tx = threadIdx.x, ty = threadIdx.y;
    #pragma unroll
    for (int i = 0; i < 8; i++) {
        int k = ty + (i << 3);
        tile[tx][k] = in[(size_t)(k0 + k) * N + n0 + tx];
    }
    __syncthreads();
    #pragma unroll
    for (int i = 0; i < 4; i++) {
        int n = ty + (i << 3);
        float a = tile[n][tx * 2], b = tile[n][tx * 2 + 1];
        *(uint32_t*)(out + (size_t)(n0 + n) * K + k0 + tx * 2) = pack_f16(a, b);
    }
}

// =================== fp16 GEMM: cp.async 4-stage, ldmatrix, mma m16n8k16 =======
static constexpr int PA = 40;                  // halves pitch (80 B)
static constexpr int TILE_B = 128 * PA * 2;    // 10240 B
static constexpr int STAGE_B = 2 * TILE_B;     // 20480 B
static constexpr uint32_t GEMM_SMEM = 4 * STAGE_B;   // 81920 B

__device__ __forceinline__ void gemm_issue(
        const __half* __restrict__ A, int lda,
        const __half* __restrict__ Bt, int ldb,
        int bm, int bn, int kt, int slot, uint32_t sbase, int tid) {
    const uint32_t dA = sbase + slot * STAGE_B;
    const __half* Ag = A + (size_t)bm * lda + (kt << 5);
    #pragma unroll
    for (int i = 0; i < 2; i++) {
        int idx = (i << 8) + tid;
        int r = idx >> 2, q = idx & 3;
        cp16(dA + r * 80 + (q << 4), Ag + (size_t)r * lda + (q << 3));
    }
    const uint32_t dB = dA + TILE_B;
    const __half* Bg = Bt + (size_t)bn * ldb + (kt << 5);
    #pragma unroll
    for (int i = 0; i < 2; i++) {
        int idx = (i << 8) + tid;
        int r = idx >> 2, q = idx & 3;
        cp16(dB + r * 80 + (q << 4), Bg + (size_t)r * ldb + (q << 3));
    }
    cp_commit();
}

template<int MODE>
__global__ void __launch_bounds__(256, 2) mma_gemm(
        const __half* __restrict__ A, int lda,
        const __half* __restrict__ Bt, int ldb,
        void* __restrict__ Cv, int ldc, int K,
        const float* __restrict__ bias,
        const float* __restrict__ xres,
        const float* __restrict__ mod) {
    extern __shared__ char smc[];
    const uint32_t sbase = smem_u32(smc);

    const int tid  = threadIdx.x;
    const int warp = tid >> 5;
    const int lane = tid & 31;
    const int g = lane >> 2, t = lane & 3;
    const int wm = (warp >> 2) * 64;
    const int wn = (warp & 3) * 32;
    const int bm = blockIdx.y << 7;
    const int bn = blockIdx.x << 7;

    const int rA = (lane & 7) + ((lane >> 3) & 1) * 8;
    const int cA = (lane >> 4) * 8;
    const int rB = (lane & 7) + (lane >> 4) * 8;
    const int cB = ((lane >> 3) & 1) * 8;
    const uint32_t aoff = ((wm + rA) * PA + cA) * 2;
    const uint32_t boff = ((wn + rB) * PA + cB) * 2;

    float acc[4][4][4];
    #pragma unroll
    for (int i = 0; i < 4; i++)
        #pragma unroll
        for (int j = 0; j < 4; j++)
            #pragma unroll
            for (int e = 0; e < 4; e++) acc[i][j][e] = 0.0f;

    const int NT = K >> 5;
    gemm_issue(A, lda, Bt, ldb, bm, bn, 0, 0, sbase, tid);
    gemm_issue(A, lda, Bt, ldb, bm, bn, 1, 1, sbase, tid);
    gemm_issue(A, lda, Bt, ldb, bm, bn, 2, 2, sbase, tid);

    for (int kt = 0; kt < NT; kt++) {
        if (kt + 2 < NT)      cp_wait<2>();
        else if (kt + 1 < NT) cp_wait<1>();
        else                  cp_wait<0>();
        __syncthreads();
        if (kt + 3 < NT)
            gemm_issue(A, lda, Bt, ldb, bm, bn, kt + 3, (kt + 3) & 3, sbase, tid);

        const uint32_t sA_b = sbase + (kt & 3) * STAGE_B;
        const uint32_t sB_b = sA_b + TILE_B;
        #pragma unroll
        for (int kk = 0; kk < 2; kk++) {
            uint32_t af[4][4], bf[4][2];
            #pragma unroll
            for (int mt = 0; mt < 4; mt++)
                ldm_x4(af[mt], sA_b + aoff + ((mt * 16 * PA + kk * 16) << 1));
            #pragma unroll
            for (int ntp = 0; ntp < 2; ntp++) {
                uint32_t tmp[4];
                ldm_x4(tmp, sB_b + boff + ((ntp * 16 * PA + kk * 16) << 1));
                bf[2*ntp][0]   = tmp[0]; bf[2*ntp][1]   = tmp[1];
                bf[2*ntp+1][0] = tmp[2]; bf[2*ntp+1][1] = tmp[3];
            }
            #pragma unroll
            for (int mt = 0; mt < 4; mt++)
                #pragma unroll
                for (int nt = 0; nt < 4; nt++)
                    mma_f16(acc[mt][nt], af[mt], bf[nt]);
        }
    }

    // ---- epilogue ----
    #pragma unroll
    for (int nt = 0; nt < 4; nt++) {
        const int col = bn + wn + (nt << 3) + (t << 1);
        const float2 bi = *(const float2*)(bias + col);
        #pragma unroll
        for (int mt = 0; mt < 4; mt++) {
            const int r0 = bm + wm + (mt << 4) + g;
            float2 v0, v1;
            v0.x = acc[mt][nt][0] + bi.x;  v0.y = acc[mt][nt][1] + bi.y;
            v1.x = acc[mt][nt][2] + bi.x;  v1.y = acc[mt][nt][3] + bi.y;
            if (MODE == 1) {
                v0.x = tanhf(v0.x); v0.y = tanhf(v0.y);
                v1.x = tanhf(v1.x); v1.y = tanhf(v1.y);
            }
            if (MODE == 2) {
                float* C = (float*)Cv;
                const int b0 = r0 >> 11;
                const float2 g2 = *(const float2*)(mod + b0*3*HIDDEN + 2*HIDDEN + col);
                const float2 x0 = *(const float2*)(xres + (size_t)r0*HIDDEN + col);
                const float2 x1 = *(const float2*)(xres + (size_t)(r0+8)*HIDDEN + col);
                v0.x = fmaf(g2.x, v0.x, x0.x); v0.y = fmaf(g2.y, v0.y, x0.y);
                v1.x = fmaf(g2.x, v1.x, x1.x); v1.y = fmaf(g2.y, v1.y, x1.y);
                *(float2*)(C + (size_t)r0 * ldc + col)       = v0;
                *(float2*)(C + (size_t)(r0 + 8) * ldc + col) = v1;
            } else {
                __half* C = (__half*)Cv;
                *(uint32_t*)(C + (size_t)r0 * ldc + col)       = pack_f16(v0.x, v0.y);
                *(uint32_t*)(C + (size_t)(r0 + 8) * ldc + col) = pack_f16(v1.x, v1.y);
            }
        }
    }
}

// =================== fp16 flash attention (3-slot KV ring) =====================
static constexpr int PQ = 72;                        // halves pitch (144 B)
static constexpr int Q_BYTES  = 128 * PQ * 2;        // 18432
static constexpr int KV_SLOT  = 64 * PQ * 2;         // 9216
static constexpr uint32_t ATTN_SMEM = Q_BYTES + 6 * KV_SLOT;  // 73728

__device__ __forceinline__ void attn_issue_kv(
        const __half* __restrict__ kh, const __half* __restrict__ vg,
        int kt, int slot, uint32_t sbase, int tid) {
    #pragma unroll
    for (int i = 0; i < 2; i++) {
        const int idx = (i << 8) + tid;
        const int r = idx >> 3, q = idx & 7;
        const int row = (kt << 6) + r;
        const uint32_t dK = sbase + Q_BYTES + slot * KV_SLOT + r * 144 + (q << 4);
        cp16(dK,                kh + (size_t)row * 64  + (q << 3));
        cp16(dK + 3 * KV_SLOT,  vg + (size_t)row * W1N + (q << 3));
    }
    cp_commit();
}

__global__ void __launch_bounds__(256, 2) attn_tc(
        const __half* __restrict__ qh, const __half* __restrict__ kh,
        const __half* __restrict__ h, __half* __restrict__ y) {
    extern __shared__ char smc[];
    __half* const smh = (__half*)smc;
    const uint32_t sbase = smem_u32(smc);

    const int tid  = threadIdx.x;
    const int warp = tid >> 5;
    const int lane = tid & 31;
    const int g = lane >> 2, t = lane & 3;
    const int bh = blockIdx.y;
    const int b = bh >> 4, hd = bh & 15;
    const int q0 = blockIdx.x << 7;

    const __half* qb = qh + (size_t)bh * LL * HEAD_DIM;
    const __half* kb = kh + (size_t)bh * LL * HEAD_DIM;
    const __half* vg = h + (size_t)b * LL * W1N + 2 * HIDDEN + hd * HEAD_DIM;

    const int rK = (lane & 7) + (lane >> 4) * 8;
    const int cK = ((lane >> 3) & 1) * 8;
    const int rV = (lane & 7) + ((lane >> 3) & 1) * 8;
    const int cV = (lane >> 4) * 8;
    const uint32_t koff = (rK * PQ + cK) * 2;
    const uint32_t voff = (rV * PQ + cV) * 2;

    #pragma unroll
    for (int i = 0; i < 4; i++) {
        int idx = (i << 8) + tid;
        int r = idx >> 3, q = idx & 7;
        *(uint4*)(smh + r * PQ + (q << 3)) =
            *(const uint4*)(qb + (size_t)(q0 + r) * 64 + (q << 3));
    }
    __syncthreads();
    uint32_t qa[4][4];
    {
        const uint32_t qoff = (((warp << 4) + rV) * PQ + cV) * 2;
        #pragma unroll
        for (int kk = 0; kk < 4; kk++)
            ldm_x4(qa[kk], sbase + qoff + ((kk * 16) << 1));
    }
    __syncthreads();

    float o[8][4];
    #pragma unroll
    for (int dn = 0; dn < 8; dn++)
        #pragma unroll
        for (int e = 0; e < 4; e++) o[dn][e] = 0.0f;
    float m0 = -1e30f, m1 = -1e30f, l0 = 0.0f, l1 = 0.0f;

    attn_issue_kv(kb, vg, 0, 0, sbase, tid);
    attn_issue_kv(kb, vg, 1, 1, sbase, tid);

    const int NT = LL / 64;
    int cur = 0, nxt = 2;
    for (int kt = 0; kt < NT; kt++) {
        if (kt + 1 < NT) cp_wait<1>(); else cp_wait<0>();
        __syncthreads();
        if (kt + 2 < NT)
            attn_issue_kv(kb, vg, kt + 2, nxt, sbase, tid);

        const uint32_t sK_b = sbase + Q_BYTES + cur * KV_SLOT;
        const uint32_t sV_b = sK_b + 3 * KV_SLOT;
        cur = (cur + 1 == 3) ? 0 : cur + 1;
        nxt = (nxt + 1 == 3) ? 0 : nxt + 1;

        float s[8][4];
        #pragma unroll
        for (int nt = 0; nt < 8; nt++)
            #pragma unroll
            for (int e = 0; e < 4; e++) s[nt][e] = 0.0f;
        #pragma unroll
        for (int kk = 0; kk < 4; kk++) {
            uint32_t kf[8][2];
            #pragma unroll
            for (int ntp = 0; ntp < 4; ntp++) {
                uint32_t tmp[4];
                ldm_x4(tmp, sK_b + koff + ((ntp * 16 * PQ + kk * 16) << 1));
                kf[2*ntp][0]   = tmp[0]; kf[2*ntp][1]   = tmp[1];
                kf[2*ntp+1][0] = tmp[2]; kf[2*ntp+1][1] = tmp[3];
            }
            #pragma unroll
            for (int nt = 0; nt < 8; nt++)
                mma_f16(s[nt], qa[kk], kf[nt]);
        }

        float mx0 = -1e30f, mx1 = -1e30f;
        #pragma unroll
        for (int nt = 0; nt < 8; nt++) {
            mx0 = fmaxf(mx0, fmaxf(s[nt][0], s[nt][1]));
            mx1 = fmaxf(mx1, fmaxf(s[nt][2], s[nt][3]));
        }
        mx0 = fmaxf(mx0, __shfl_xor_sync(0xffffffffu, mx0, 1));
        mx0 = fmaxf(mx0, __shfl_xor_sync(0xffffffffu, mx0, 2));
        mx1 = fmaxf(mx1, __shfl_xor_sync(0xffffffffu, mx1, 1));
        mx1 = fmaxf(mx1, __shfl_xor_sync(0xffffffffu, mx1, 2));
        const float M0 = fmaxf(m0, mx0), M1 = fmaxf(m1, mx1);
        const float f0 = __expf(m0 - M0), f1 = __expf(m1 - M1);
        m0 = M0; m1 = M1;

        float sum0 = 0.0f, sum1 = 0.0f;
        #pragma unroll
        for (int nt = 0; nt < 8; nt++) {
            s[nt][0] = __expf(s[nt][0] - M0);
            s[nt][1] = __expf(s[nt][1] - M0);
            s[nt][2] = __expf(s[nt][2] - M1);
            s[nt][3] = __expf(s[nt][3] - M1);
            sum0 += s[nt][0] + s[nt][1];
            sum1 += s[nt][2] + s[nt][3];
        }
        sum0 += __shfl_xor_sync(0xffffffffu, sum0, 1);
        sum0 += __shfl_xor_sync(0xffffffffu, sum0, 2);
        sum1 += __shfl_xor_sync(0xffffffffu, sum1, 1);
        sum1 += __shfl_xor_sync(0xffffffffu, sum1, 2);
        l0 = l0 * f0 + sum0;
        l1 = l1 * f1 + sum1;

        #pragma unroll
        for (int dn = 0; dn < 8; dn++) {
            o[dn][0] *= f0; o[dn][1] *= f0;
            o[dn][2] *= f1; o[dn][3] *= f1;
        }

        uint32_t pa[4][4];
        #pragma unroll
        for (int kc = 0; kc < 4; kc++) {
            pa[kc][0] = pack_f16(s[2*kc][0],   s[2*kc][1]);
            pa[kc][1] = pack_f16(s[2*kc][2],   s[2*kc][3]);
            pa[kc][2] = pack_f16(s[2*kc+1][0], s[2*kc+1][1]);
            pa[kc][3] = pack_f16(s[2*kc+1][2], s[2*kc+1][3]);
        }

        #pragma unroll
        for (int kc = 0; kc < 4; kc++) {
            #pragma unroll
            for (int dnp = 0; dnp < 4; dnp++) {
                uint32_t tmp[4];
                ldm_x4_t(tmp, sV_b + voff + ((kc * 16 * PQ + dnp * 16) << 1));
                mma_f16(o[2*dnp],   pa[kc], tmp);
                mma_f16(o[2*dnp+1], pa[kc], tmp + 2);
            }
        }
    }

    const float il0 = 1.0f / l0, il1 = 1.0f / l1;
    const int row0 = b * LL + q0 + (warp << 4) + g;
    __half* yp0 = y + (size_t)row0 * (2*HIDDEN) + hd * HEAD_DIM + (t << 1);
    __half* yp1 = yp0 + (size_t)8 * (2*HIDDEN);
    #pragma unroll
    for (int dn = 0; dn < 8; dn++) {
        *(uint32_t*)(yp0 + (dn << 3)) = pack_f16(o[dn][0] * il0, o[dn][1] * il0);
        *(uint32_t*)(yp1 + (dn << 3)) = pack_f16(o[dn][2] * il1, o[dn][3] * il1);
    }
}

// ---------------- mod GEMV: split-K(16) partial + reduce ------------------------
__global__ void __launch_bounds__(256) mod_partial(
        const float* __restrict__ vec, const float* __restrict__ w_mod,
        float* __restrict__ modp) {
    __shared__ float sv[64];
    const int b = blockIdx.z, ks = blockIdx.y;
    const int n = blockIdx.x * 256 + threadIdx.x;
    if (threadIdx.x < 64) {
        float v = vec[b * HIDDEN + ks * 64 + threadIdx.x];
        sv[threadIdx.x] = v / (1.0f + expf(-v));
    }
    __syncthreads();
    float acc = 0.0f;
    const float* W = w_mod + (size_t)(ks * 64) * (3 * HIDDEN) + n;
    #pragma unroll 8
    for (int k = 0; k < 64; k++)
        acc = fmaf(sv[k], W[(size_t)k * (3 * HIDDEN)], acc);
    modp[((ks * BB) + b) * (3 * HIDDEN) + n] = acc;
}

__global__ void __launch_bounds__(256) mod_reduce(
        const float* __restrict__ modp, const float* __restrict__ b_mod,
        float* __restrict__ mod) {
    const int idx = blockIdx.x * 256 + threadIdx.x;
    const int b = idx / (3 * HIDDEN), n = idx % (3 * HIDDEN);
    float s = b_mod[n];
    #pragma unroll
    for (int ks = 0; ks < 16; ks++)
        s += modp[((ks * BB) + b) * (3 * HIDDEN) + n];
    mod[idx] = s;
}

// ---------------- kernel 2: layernorm + modulate -> fp16 ------------------------
__global__ void __launch_bounds__(256) ln_mod_kernel(const float* __restrict__ x,
                                                     const float* __restrict__ mod,
                                                     __half* __restrict__ xmod) {
    __shared__ float sbuf[8];
    __shared__ float s_mean, s_rstd;
    int token = blockIdx.x;
    int b = token >> 11;
    int tid = threadIdx.x;
    const float4 xv = ((const float4*)(x + (size_t)token*HIDDEN))[tid];

    float s = xv.x + xv.y + xv.z + xv.w;
    #pragma unroll
    for (int o = 16; o > 0; o >>= 1) s += __shfl_xor_sync(0xffffffffu, s, o);
    if ((tid & 31) == 0) sbuf[tid >> 5] = s;
    __syncthreads();
    if (tid == 0) {
        float tq = 0;
        #pragma unroll
        for (int i = 0; i < 8; i++) tq += sbuf[i];
        s_mean = tq * (1.0f / HIDDEN);
    }
    __syncthreads();
    float m = s_mean;
    float dx = xv.x - m, dy = xv.y - m, dz = xv.z - m, dw = xv.w - m;
    float ss = dx*dx + dy*dy + dz*dz + dw*dw;
    #pragma unroll
    for (int o = 16; o > 0; o >>= 1) ss += __shfl_xor_sync(0xffffffffu, ss, o);
    __syncthreads();
    if ((tid & 31) == 0) sbuf[tid >> 5] = ss;
    __syncthreads();
    if (tid == 0) {
        float tq = 0;
        #pragma unroll
        for (int i = 0; i < 8; i++) tq += sbuf[i];
        s_rstd = rsqrtf(tq * (1.0f / HIDDEN) + 1e-6f);
    }
    __syncthreads();
    float r = s_rstd;
    int c = tid * 4;
    const float4 sh = *(const float4*)(mod + b*3*HIDDEN + c);
    const float4 sc = *(const float4*)(mod + b*3*HIDDEN + HIDDEN + c);
    float o0 = fmaf(1.0f + sc.x, dx*r, sh.x);
    float o1 = fmaf(1.0f + sc.y, dy*r, sh.y);
    float o2 = fmaf(1.0f + sc.z, dz*r, sh.z);
    float o3 = fmaf(1.0f + sc.w, dw*r, sh.w);
    uint32_t* dst = (uint32_t*)(xmod + (size_t)token*HIDDEN + c);
    dst[0] = pack_f16(o0, o1);
    dst[1] = pack_f16(o2, o3);
}

// ---------------- kernel 4: RMSNorm + RoPE, fp16 h -> per-head q/k ---------------
__global__ void __launch_bounds__(512) qk_norm_rope_kernel(
        const __half* __restrict__ h,
        const float* __restrict__ pe,
        const float* __restrict__ q_scale,
        const float* __restrict__ k_scale,
        __half* __restrict__ qh, __half* __restrict__ kh) {
    int token = blockIdx.x;
    int l = token & (LL - 1);
    int b = token >> 11;
    int head = threadIdx.x >> 5;
    int lane = threadIdx.x & 31;

    const __half* hq = h + (size_t)token*W1N + head*HEAD_DIM;
    const size_t oidx = ((size_t)(b*HEADS + head)*LL + l)*HEAD_DIM + lane*2;

    const float4 p = *(const float4*)(pe + (size_t)l*128 + lane*4);
    float sx = q_scale[lane*2], sy = q_scale[lane*2+1];
    float kx = k_scale[lane*2], ky = k_scale[lane*2+1];

    {
        float2 q2 = __half22float2(*(const __half2*)(hq + lane*2));
        float ss = q2.x*q2.x + q2.y*q2.y;
        #pragma unroll
        for (int o = 16; o > 0; o >>= 1) ss += __shfl_xor_sync(0xffffffffu, ss, o);
        float rr = rsqrtf(ss * (1.0f/HEAD_DIM) + 1e-6f);
        float t0 = q2.x * rr * sx, t1 = q2.y * rr * sy;
        *(uint32_t*)(qh + oidx) =
            pack_f16(0.125f*(p.x*t0 + p.y*t1), 0.125f*(p.z*t0 + p.w*t1));
    }
    {
        float2 k2 = __half22float2(*(const __half2*)(hq + HIDDEN + lane*2));
        float ss = k2.x*k2.x + k2.y*k2.y;
        #pragma unroll
        for (int o = 16; o > 0; o >>= 1) ss += __shfl_xor_sync(0xffffffffu, ss, o);
        float rr = rsqrtf(ss * (1.0f/HEAD_DIM) + 1e-6f);
        float t0 = k2.x * rr * kx, t1 = k2.y * rr * ky;
        *(uint32_t*)(kh + oidx) = pack_f16(p.x*t0 + p.y*t1, p.z*t0 + p.w*t1);
    }
}

// ---------------- launch --------------------------------------------------------
extern "C" void kernel_launch(void* const* d_in, const int* in_sizes, int n_in,
                              void* d_out, int out_size) {
    const float* x       = (const float*)d_in[0];
    const float* vec     = (const float*)d_in[1];
    const float* pe      = (const float*)d_in[2];
    const float* w_mod   = (const float*)d_in[3];
    const float* b_mod   = (const float*)d_in[4];
    const float* w1      = (const float*)d_in[5];
    const float* b1      = (const float*)d_in[6];
    const float* w_mlp   = (const float*)d_in[7];
    const float* b_mlp   = (const float*)d_in[8];
    const float* w2      = (const float*)d_in[9];
    const float* b2      = (const float*)d_in[10];
    const float* q_scale = (const float*)d_in[11];
    const float* k_scale = (const float*)d_in[12];
    float* out = (float*)d_out;

    float *mod, *modp;
    __half *xmod, *h, *qh, *kh, *y, *w1t, *wmlpt, *w2t;
    cudaGetSymbolAddress((void**)&mod,   g_mod);
    cudaGetSymbolAddress((void**)&modp,  g_modp);
    cudaGetSymbolAddress((void**)&xmod,  g_xmod);
    cudaGetSymbolAddress((void**)&h,     g_h);
    cudaGetSymbolAddress((void**)&qh,    g_qh);
    cudaGetSymbolAddress((void**)&kh,    g_kh);
    cudaGetSymbolAddress((void**)&y,     g_y);
    cudaGetSymbolAddress((void**)&w1t,   g_w1t);
    cudaGetSymbolAddress((void**)&wmlpt, g_wmlpt);
    cudaGetSymbolAddress((void**)&w2t,   g_w2t);

    static cudaStream_t s1 = nullptr;
    static cudaEvent_t evF = nullptr, evW1 = nullptr, evH = nullptr, evMLP = nullptr;
    if (!s1) {
        cudaStreamCreateWithFlags(&s1, cudaStreamNonBlocking);
        cudaEventCreateWithFlags(&evF,   cudaEventDisableTiming);
        cudaEventCreateWithFlags(&evW1,  cudaEventDisableTiming);
        cudaEventCreateWithFlags(&evH,   cudaEventDisableTiming);
        cudaEventCreateWithFlags(&evMLP, cudaEventDisableTiming);
        cudaFuncSetAttribute(mma_gemm<0>, cudaFuncAttributeMaxDynamicSharedMemorySize, GEMM_SMEM);
        cudaFuncSetAttribute(mma_gemm<1>, cudaFuncAttributeMaxDynamicSharedMemorySize, GEMM_SMEM);
        cudaFuncSetAttribute(mma_gemm<2>, cudaFuncAttributeMaxDynamicSharedMemorySize, GEMM_SMEM);
        cudaFuncSetAttribute(attn_tc,     cudaFuncAttributeMaxDynamicSharedMemorySize, ATTN_SMEM);
    }

    // fork side stream from main (legacy) stream
    cudaEventRecord(evF, 0);
    cudaStreamWaitEvent(s1, evF, 0);

    // side: weight transposes (w1t first; it gates GEMM0)
    transpose_h<<<dim3(W1N/32, HIDDEN/64), dim3(32,8), 0, s1>>>(w1, w1t, HIDDEN, W1N);
    cudaEventRecord(evW1, s1);
    transpose_h<<<dim3(HIDDEN/32, MLPH/64),     dim3(32,8), 0, s1>>>(w_mlp, wmlpt, MLPH,     HIDDEN);
    transpose_h<<<dim3(HIDDEN/32, 2*HIDDEN/64), dim3(32,8), 0, s1>>>(w2,    w2t,   2*HIDDEN, HIDDEN);

    // main: modulation + layernorm (concurrent with transposes)
    mod_partial<<<dim3(3*HIDDEN/256, 16, BB), 256>>>(vec, w_mod, modp);
    mod_reduce<<<BB*3*HIDDEN/256, 256>>>(modp, b_mod, mod);
    ln_mod_kernel<<<NTOK, 256>>>(x, mod, xmod);

    // main: GEMM0 (needs xmod + w1t)
    cudaStreamWaitEvent(0, evW1, 0);
    mma_gemm<0><<<dim3(W1N/128, NTOK/128), 256, GEMM_SMEM>>>(
        xmod, HIDDEN, w1t, HIDDEN, h, W1N, HIDDEN, b1, nullptr, nullptr);
    cudaEventRecord(evH, 0);

    // side: MLP GEMM (needs h + wmlpt), overlaps rope+attn on main
    cudaStreamWaitEvent(s1, evH, 0);
    mma_gemm<1><<<dim3(HIDDEN/128, NTOK/128), 256, GEMM_SMEM, s1>>>(
        h + 3*HIDDEN, W1N, wmlpt, MLPH, y + HIDDEN, 2*HIDDEN,
        MLPH, b_mlp, nullptr, nullptr);
    cudaEventRecord(evMLP, s1);

    // main: rope + attention (V read directly from h inside attn)
    qk_norm_rope_kernel<<<NTOK, 512>>>(h, pe, q_scale, k_scale, qh, kh);
    attn_tc<<<dim3(LL/128, BB*HEADS), 256, ATTN_SMEM>>>(qh, kh, h, y);

    // join, final GEMM (full K=2048, fused epilogue)
    cudaStreamWaitEvent(0, evMLP, 0);
    mma_gemm<2><<<dim3(HIDDEN/128, NTOK/128), 256, GEMM_SMEM>>>(
        y, 2*HIDDEN, w2t, 2*HIDDEN, out, HIDDEN,
        2*HIDDEN, b2, x, mod);
}